// round 10
// baseline (speedup 1.0000x reference)
#include <cuda_runtime.h>

// WeightedDistanceTransform — 3-kernel pipeline (R7 structure; k2 min-plus branch-free d<=3).
// k1: bitmask pack (ballot) -> 1-bit mask scratch
// k2: g^2 on the fly (clz/ffs) into 3-row-padded smem tile; vertical min-plus:
//     7 independent LDS (d=0..3, branch-free) + rare exact escape loop (best>16);
//     dt write + per-slice atomicMax.
// k3: inverted normalize (mx - dt)/mx.

#define HH 256
#define WW 256
#define NPIX (HH * WW)
#define BIG 512
#define MAXSLICES 64
#define WPR 8
#define SLICE_WORDS (HH * WPR)        // 2048
#define BIGVAL (1 << 28)

__device__ unsigned int maskbuf[MAXSLICES * SLICE_WORDS];
__device__ unsigned int mx_bits[MAXSLICES];

// ---------------- Kernel 1: mask pack (R4 version, verbatim) ----------------
#define K1_THREADS 256

__global__ __launch_bounds__(K1_THREADS)
void k1_mask(const float* __restrict__ in) {
    const int slice = blockIdx.x >> 4;
    const int rb    = blockIdx.x & 15;
    const int tid   = threadIdx.x;

    if (rb == 0 && tid == 0) mx_bits[slice] = 0u;        // reset before k2

    const float4* s4 = reinterpret_cast<const float4*>(in)
                     + (size_t)slice * (NPIX / 4) + (size_t)rb * 1024 + tid * 4;
    float4 a = s4[0], b = s4[1], c = s4[2], d = s4[3];
    unsigned m = 0;
    m |= (a.x != 0.0f) << 0;  m |= (a.y != 0.0f) << 1;
    m |= (a.z != 0.0f) << 2;  m |= (a.w != 0.0f) << 3;
    m |= (b.x != 0.0f) << 4;  m |= (b.y != 0.0f) << 5;
    m |= (b.z != 0.0f) << 6;  m |= (b.w != 0.0f) << 7;
    m |= (c.x != 0.0f) << 8;  m |= (c.y != 0.0f) << 9;
    m |= (c.z != 0.0f) << 10; m |= (c.w != 0.0f) << 11;
    m |= (d.x != 0.0f) << 12; m |= (d.y != 0.0f) << 13;
    m |= (d.z != 0.0f) << 14; m |= (d.w != 0.0f) << 15;
    unsigned other = __shfl_xor_sync(0xffffffffu, m, 1);
    if ((tid & 1) == 0) {
        maskbuf[slice * SLICE_WORDS + rb * 128 + (tid >> 1)] = m | (other << 16);
    }
}

// ---------------- Kernel 2: g^2 + branch-free min-plus ----------------
#define K2_COLS 16
#define K2_THREADS 512
#define PADR 3

__global__ __launch_bounds__(K2_THREADS)
void k2_passB(float* __restrict__ out) {
    __shared__ unsigned int M[SLICE_WORDS];                   // 8 KB slice bitmask
    __shared__ unsigned int g2t[(HH + 2 * PADR) * K2_COLS];   // padded g^2 tile
    __shared__ float red[K2_THREADS / 32];

    const int slice = blockIdx.x >> 4;            // 16 strips per slice
    const int st    = blockIdx.x & 15;
    const int c0    = st * K2_COLS;
    const int tid   = threadIdx.x;

    // load slice bitmask: 4 words/thread
    {
        const unsigned int* src = maskbuf + slice * SLICE_WORDS;
        #pragma unroll
        for (int k = 0; k < SLICE_WORDS / K2_THREADS; ++k)
            M[k * K2_THREADS + tid] = src[k * K2_THREADS + tid];
    }
    // pad rows (3 top + 3 bottom) = 96 words
    if (tid < 2 * PADR * K2_COLS) {
        int rr = tid / K2_COLS, cc = tid % K2_COLS;
        int row = (rr < PADR) ? rr : rr + HH;
        g2t[row * K2_COLS + cc] = BIGVAL;
    }
    __syncthreads();

    // g^2 for the strip: 8 px/thread via clz/ffs on row bitmask
    #pragma unroll
    for (int it = 0; it < (HH * K2_COLS) / K2_THREADS; ++it) {
        int i = it * K2_THREADS + tid;
        int r = i >> 4;
        int w = c0 + (i & 15);
        const unsigned int* Mr = M + r * WPR;
        int ci = w >> 5, b = w & 31;

        int ld = BIG;                                          // nearest zero <= w
        unsigned lmask = (b == 31) ? 0xffffffffu : ((2u << b) - 1u);
        unsigned z = (~Mr[ci]) & lmask;
        if (z) {
            ld = b - (31 - __clz(z));
        } else {
            for (int cj = ci - 1; cj >= 0; --cj) {
                unsigned zz = ~Mr[cj];
                if (zz) { ld = (ci - cj) * 32 + b - (31 - __clz(zz)); break; }
            }
        }
        int rd = BIG;                                          // nearest zero >= w
        z = (~Mr[ci]) >> b;
        if (z) {
            rd = __ffs(z) - 1;
        } else {
            for (int cj = ci + 1; cj < WPR; ++cj) {
                unsigned zz = ~Mr[cj];
                if (zz) { rd = cj * 32 + (__ffs(zz) - 1) - w; break; }
            }
        }
        int g = min(min(ld, rd), BIG);
        g2t[(r + PADR) * K2_COLS + (i & 15)] = (unsigned)(g * g);
    }
    __syncthreads();

    const float wts[3] = {0.5f, 1.0f, 2.0f};
    const float wc = wts[slice % 3];
    float* dst = out + (size_t)slice * NPIX;

    float lmax = 0.0f;
    #pragma unroll
    for (int it = 0; it < (HH * K2_COLS) / K2_THREADS; ++it) {
        int i = it * K2_THREADS + tid;
        int r = i >> 4, c = i & 15;
        const unsigned int* col = g2t + (r + PADR) * K2_COLS + c;

        // branch-free d=0..3: 7 independent LDS, fully pipelined
        int b0 = (int)col[0];
        int b1 = (int)min(col[-K2_COLS],     col[K2_COLS])     + 1;
        int b2 = (int)min(col[-2 * K2_COLS], col[2 * K2_COLS]) + 4;
        int b3 = (int)min(col[-3 * K2_COLS], col[3 * K2_COLS]) + 9;
        int best = min(min(b0, b1), min(b2, b3));

        if (best > 16) {                       // rare exact escape: d>=4 candidates
            for (int d = 4; d < HH; ++d) {
                int dd = d * d;
                if (dd >= best) break;         // exact: candidates >= d^2
                int up = r - d, dn = r + d;
                if (up >= 0) best = min(best, (int)g2t[(up + PADR) * K2_COLS + c] + dd);
                if (dn < HH) best = min(best, (int)g2t[(dn + PADR) * K2_COLS + c] + dd);
            }
        }
        float dt = wc * sqrtf((float)best);
        dst[r * WW + c0 + c] = dt;
        lmax = fmaxf(lmax, dt);
    }

    #pragma unroll
    for (int o = 16; o; o >>= 1) lmax = fmaxf(lmax, __shfl_xor_sync(0xffffffffu, lmax, o));
    if ((tid & 31) == 0) red[tid >> 5] = lmax;
    __syncthreads();
    if (tid < 16) {
        float v = red[tid];
        #pragma unroll
        for (int o = 8; o; o >>= 1) v = fmaxf(v, __shfl_xor_sync(0x0000ffffu, v, o, 16));
        if (tid == 0) atomicMax(&mx_bits[slice], __float_as_uint(v));  // dt>=0: bit-monotone
    }
}

// ---------------- Kernel 3: normalize (R4 version, verbatim) ----------------
#define K3_THREADS 256

__global__ __launch_bounds__(K3_THREADS)
void k3_norm(float* __restrict__ out) {
    const int slice = blockIdx.x >> 4;
    const int bl    = blockIdx.x & 15;
    const float mx  = __uint_as_float(mx_bits[slice]);
    const float inv = (mx > 0.0f) ? (1.0f / mx) : 0.0f;   // mx==0 -> dt==0 -> out 0

    float4* p = reinterpret_cast<float4*>(out) + (size_t)slice * (NPIX / 4) + bl * 1024;
    #pragma unroll
    for (int k = 0; k < 4; ++k) {
        int j = k * K3_THREADS + threadIdx.x;
        float4 v = p[j];
        v.x = (mx - v.x) * inv;
        v.y = (mx - v.y) * inv;
        v.z = (mx - v.z) * inv;
        v.w = (mx - v.w) * inv;
        p[j] = v;
    }
}

extern "C" void kernel_launch(void* const* d_in, const int* in_sizes, int n_in,
                              void* d_out, int out_size) {
    const float* in = (const float*)d_in[0];
    float* out = (float*)d_out;
    const int nslices = in_sizes[0] / NPIX;       // 48 for [16,3,256,256]

    k1_mask <<<nslices * 16, K1_THREADS>>>(in);
    k2_passB<<<nslices * 16, K2_THREADS>>>(out);
    k3_norm <<<nslices * 16, K3_THREADS>>>(out);
}